// round 15
// baseline (speedup 1.0000x reference)
#include <cuda_runtime.h>
#include <cuda_bf16.h>
#include <cstdint>

// Shapes:
//  x [16,64,64,64] f32 NCHW, W_off [18,64,3,3], b_off[18], W_k [128,64,3,3], b_k[128]
//  out [16,128,64,64]

#define BB 16
#define CC 64
#define HH 64
#define WW 64
#define OCC 128
#define NOFF 18

// ---------------- scratch ----------------
__device__ float g_xt[BB * HH * WW * CC];          // NHWC x
__device__ float g_off[BB * NOFF * HH * WW];       // offsets planar
__device__ __nv_bfloat16 g_wb[9 * 2 * CC * OCC];   // k_main weights [tap][hi/lo][c][128oc] swizzled
__device__ __nv_bfloat16 g_wo2[5 * 2 * CC * 64];   // k_off weights: [pair][hi/lo][c][2taps x 32oc] swizzled

// swizzles
#define SW128(o) ((o) ^ (((o) >> 3) & 0x70))   // 128B rows
#define SWB(o)   ((o) ^ (((o) >> 4) & 0x70))   // 256B rows

__device__ __forceinline__ uint32_t smem_u32(const void* p) {
    uint32_t a;
    asm("{ .reg .u64 t; cvta.to.shared.u64 t, %1; cvt.u32.u64 %0, t; }" : "=r"(a) : "l"(p));
    return a;
}

__device__ __forceinline__ void ldmA(uint32_t* r, uint32_t base, int m0, int k0, int lane) {
    uint32_t off = (uint32_t)(m0 + (lane & 15)) * 128u + (uint32_t)(k0 + ((lane >> 4) & 1) * 8) * 2u;
    uint32_t addr = base + SW128(off);
    asm volatile("ldmatrix.sync.aligned.m8n8.x4.shared.b16 {%0,%1,%2,%3}, [%4];"
                 : "=r"(r[0]), "=r"(r[1]), "=r"(r[2]), "=r"(r[3]) : "r"(addr));
}
// B in 256B rows (k_main)
__device__ __forceinline__ void ldmB(uint32_t* r, uint32_t base, int n0, int k0, int lane) {
    uint32_t off = (uint32_t)(k0 + (lane & 15)) * 256u + (uint32_t)(n0 + ((lane >> 4) & 1) * 8) * 2u;
    uint32_t addr = base + SWB(off);
    asm volatile("ldmatrix.sync.aligned.m8n8.x4.trans.shared.b16 {%0,%1,%2,%3}, [%4];"
                 : "=r"(r[0]), "=r"(r[1]), "=r"(r[2]), "=r"(r[3]) : "r"(addr));
}
// B in 128B rows (k_off2)
__device__ __forceinline__ void ldmB2(uint32_t* r, uint32_t base, int n0, int k0, int lane) {
    uint32_t off = (uint32_t)(k0 + (lane & 15)) * 128u + (uint32_t)(n0 + ((lane >> 4) & 1) * 8) * 2u;
    uint32_t addr = base + SW128(off);
    asm volatile("ldmatrix.sync.aligned.m8n8.x4.trans.shared.b16 {%0,%1,%2,%3}, [%4];"
                 : "=r"(r[0]), "=r"(r[1]), "=r"(r[2]), "=r"(r[3]) : "r"(addr));
}
__device__ __forceinline__ void mma16816(float* c, const uint32_t* a, const uint32_t* b) {
    asm volatile("mma.sync.aligned.m16n8k16.row.col.f32.bf16.bf16.f32 "
                 "{%0,%1,%2,%3}, {%4,%5,%6,%7}, {%8,%9}, {%0,%1,%2,%3};"
                 : "+f"(c[0]), "+f"(c[1]), "+f"(c[2]), "+f"(c[3])
                 : "r"(a[0]), "r"(a[1]), "r"(a[2]), "r"(a[3]), "r"(b[0]), "r"(b[1]));
}

#define CP_ASYNC16(dst, src) \
    asm volatile("cp.async.cg.shared.global [%0], [%1], 16;" ::"r"(dst), "l"(src) : "memory")
#define CP_COMMIT() asm volatile("cp.async.commit_group;" ::: "memory")
#define CP_WAIT0()  asm volatile("cp.async.wait_group 0;" ::: "memory")

// ---------------- kernel P: fused prep (transpose + both weight repacks) ----------------
// grid: [0,1024) transpose, [1024,1312) W_k repack (288 blocks), [1312,1384) W_off repack (72)
__global__ __launch_bounds__(256) void k_prep(const float* __restrict__ x,
                                              const float* __restrict__ Wk,
                                              const float* __restrict__ Woff) {
    __shared__ float tile[64][65];
    int bx = blockIdx.x;
    int tid = threadIdx.x;

    if (bx < 1024) {
        // ---- NCHW -> NHWC transpose ----
        int b = bx >> 6, y = bx & 63;
        int lo = tid & 63, hi = tid >> 6;
#pragma unroll
        for (int rep = 0; rep < 16; rep++) {
            int c = rep * 4 + hi;
            tile[c][lo] = x[((b * CC + c) * HH + y) * WW + lo];
        }
        __syncthreads();
#pragma unroll
        for (int rep = 0; rep < 16; rep++) {
            int xcol = rep * 4 + hi;
            g_xt[((b * HH + y) * WW + xcol) * CC + lo] = tile[lo][xcol];
        }
    } else if (bx < 1312) {
        // ---- W_k -> swizzled bf16 hi/lo [tap][hi/lo][c][128oc] ----
        int idx = (bx - 1024) * 256 + tid;
        if (idx < 9 * OCC * CC) {
            int oc = idx & 127;
            int c = (idx >> 7) & 63;
            int n = idx >> 13;
            float v = Wk[(oc * CC + c) * 9 + n];
            __nv_bfloat16 hi = __float2bfloat16(v);
            __nv_bfloat16 lo = __float2bfloat16(v - __bfloat162float(hi));
            uint32_t off = (uint32_t)c * 256 + (uint32_t)oc * 2;
            uint32_t sw = SWB(off);
            g_wb[(n * 2 + 0) * (CC * OCC) + sw / 2] = hi;
            g_wb[(n * 2 + 1) * (CC * OCC) + sw / 2] = lo;
        }
    } else {
        // ---- W_off -> pair-packed swizzled bf16 hi/lo ----
        int idx = (bx - 1312) * 256 + tid;
        if (idx < 9 * CC * 32) {
            int oc = idx & 31;
            int c = (idx >> 5) & 63;
            int tap = idx >> 11;
            float v = (oc < NOFF) ? Woff[(oc * CC + c) * 9 + tap] : 0.f;
            __nv_bfloat16 hi = __float2bfloat16(v);
            __nv_bfloat16 lo = __float2bfloat16(v - __bfloat162float(hi));
            int pair = tap >> 1;
            int slot = (tap & 1) * 32 + oc;
            uint32_t sw = SW128((uint32_t)c * 128 + (uint32_t)slot * 2);
            g_wo2[(pair * 2 + 0) * (CC * 64) + sw / 2] = hi;
            g_wo2[(pair * 2 + 1) * (CC * 64) + sw / 2] = lo;
        }
    }
}

extern __shared__ char dsm_raw[];

// ---------------- kernel B: offset conv, M=64 (1 row/CTA), 3 CTAs/SM ----------------
// block = (b, row i0), grid 64x16. M=64 px, N=32 (18 padded), K=9x64.
// A: 3 extended row-tiles hi+lo = 50.7KB (built once).
// B: single 16KB pair buffer streamed via cp.async. Total 68KB -> 3 CTAs/SM.
#define ATILE 8448   // 66 * 128 bytes
__global__ __launch_bounds__(256, 3)
void k_off2(const float* __restrict__ boff) {
    int b = blockIdx.y, i0 = blockIdx.x;
    int tid = threadIdx.x, wid = tid >> 5, lane = tid & 31;
    int mw = wid >> 1, nw = wid & 1;   // m-warp 0..3 (16px), n-warp 0..1 (16oc)
    int jbase = mw * 16;

    uint32_t raw = smem_u32(dsm_raw);
    uint32_t base = (raw + 1023) & ~1023u;
    char* abase = dsm_raw + (base - raw);
    uint32_t A_hi = base, A_lo = base + 3 * ATILE;
    uint32_t B_base = base + 6 * ATILE;           // 50688; single 16KB buffer
    const float* gxt_b = g_xt + (size_t)b * HH * WW * CC;

    auto issueBp = [&](int pair) {
        uint32_t dst = B_base + (uint32_t)tid * 16;
        const char* src = (const char*)g_wo2 + pair * 16384 + tid * 16;
#pragma unroll
        for (int v = 0; v < 4; v++) CP_ASYNC16(dst + v * 4096, src + v * 4096);
        CP_COMMIT();
    };

    issueBp(0);

    // ---- A: build 3 extended row-tiles once (rows i0-1, i0, i0+1) ----
    for (int mi = wid; mi < 3 * 66; mi += 8) {
        int tile = mi / 66, m = mi % 66;
        int row = i0 + tile - 1, col = m - 1;
        bool ok = (row >= 0) && (row < HH) && (col >= 0) && (col < WW);
        float2 v = ok ? __ldg((const float2*)(gxt_b + (row * WW + col) * CC) + lane)
                      : make_float2(0.f, 0.f);
        __nv_bfloat162 hi2 = __float22bfloat162_rn(v);
        float hxf = __bfloat162float(hi2.x), hyf = __bfloat162float(hi2.y);
        __nv_bfloat162 lo2 = __float22bfloat162_rn(make_float2(v.x - hxf, v.y - hyf));
        uint32_t sw = SW128((uint32_t)m * 128 + (uint32_t)lane * 4);
        *(__nv_bfloat162*)(abase + tile * ATILE + sw) = hi2;
        *(__nv_bfloat162*)(abase + 3 * ATILE + tile * ATILE + sw) = lo2;
    }

    float acc[2][4];
#pragma unroll
    for (int h = 0; h < 2; h++)
#pragma unroll
        for (int q = 0; q < 4; q++) acc[h][q] = 0.f;

#pragma unroll
    for (int pair = 0; pair < 5; pair++) {
        CP_WAIT0();
        __syncthreads();     // B[pair] ready; A published (pair 0); MMA(pair-1) done

#pragma unroll
        for (int t2 = 0; t2 < 2; t2++) {
            int tap = pair * 2 + t2;
            if (tap >= 9) break;
            int dxk = tap / 3 - 1, dyk = tap % 3 - 1;
            int tile = dxk + 1;                       // 0..2
            uint32_t Ah = A_hi + tile * ATILE;
            uint32_t Al = A_lo + tile * ATILE;
            int n0 = t2 * 32 + nw * 16;
            int mA0 = jbase + dyk + 1;
#pragma unroll
            for (int ks = 0; ks < 4; ks++) {
                int k0 = ks * 16;
                uint32_t ah[4], al[4], bh[4], bl[4];
                ldmA(ah, Ah, mA0, k0, lane);
                ldmA(al, Al, mA0, k0, lane);
                ldmB2(bh, B_base, n0, k0, lane);
                ldmB2(bl, B_base + 8192, n0, k0, lane);
#pragma unroll
                for (int h = 0; h < 2; h++) {
                    mma16816(acc[h], ah, bh + 2 * h);
                    mma16816(acc[h], al, bh + 2 * h);
                    mma16816(acc[h], ah, bl + 2 * h);
                }
            }
        }

        if (pair < 4) {
            __syncthreads();     // all MMAs done reading B before overwrite
            issueBp(pair + 1);
        }
    }

    // ---- epilogue: oc < 18 only ----
    int gi = lane >> 2, t4 = lane & 3;
    int j0 = jbase + gi, j1 = j0 + 8;
#pragma unroll
    for (int h = 0; h < 2; h++) {
        int o = nw * 16 + h * 8 + t4 * 2;
        if (o < NOFF) {
            float bv0 = __ldg(&boff[o]);
            float* dst0 = &g_off[((b * NOFF + o) * HH + i0) * WW];
            dst0[j0] = acc[h][0] + bv0;
            dst0[j1] = acc[h][2] + bv0;
            if (o + 1 < NOFF) {
                float bv1 = __ldg(&boff[o + 1]);
                float* dst1 = &g_off[((b * NOFF + o + 1) * HH + i0) * WW];
                dst1[j0] = acc[h][1] + bv1;
                dst1[j1] = acc[h][3] + bv1;
            }
        }
    }
}

// ---------------- kernel D: pipelined sampling (LDG.128 paired-lane) + HMMA 2m x 4n ----------------
__global__ __launch_bounds__(256, 3)
void k_main(const float* __restrict__ bk, float* __restrict__ out) {
    __shared__ float OFF[NOFF][64];

    int b = blockIdx.y, i0 = blockIdx.x;
    int tid = threadIdx.x, wid = tid >> 5, lane = tid & 31;
    int mw = wid >> 2, nw4 = wid & 3;   // 2 m-warps (32px), 4 n-warps (32oc)
    int m0 = mw * 32, nbase = nw4 * 32;

    uint32_t raw = smem_u32(dsm_raw);
    uint32_t base = (raw + 1023) & ~1023u;
    char* abase = dsm_raw + (base - raw);
    const float* gxt_b = g_xt + (size_t)b * HH * WW * CC;
    uint32_t B_base = base + 32768;

    for (int t = tid; t < NOFF * 64; t += 256) {
        int o = t >> 6, j = t & 63;
        OFF[o][j] = g_off[((b * NOFF + o) * HH + i0) * WW + j];
    }

    float acc[2][4][4];
#pragma unroll
    for (int mi = 0; mi < 2; mi++)
#pragma unroll
        for (int ni = 0; ni < 4; ni++)
#pragma unroll
            for (int q = 0; q < 4; q++) acc[mi][ni][q] = 0.f;

    auto issueB = [&](int tap) {
        uint32_t dst = B_base + (uint32_t)tid * 16;
        const char* src = (const char*)(g_wb + tap * 2 * (CC * OCC)) + tid * 16;
#pragma unroll
        for (int v = 0; v < 8; v++) CP_ASYNC16(dst + v * 4096, src + v * 4096);
        CP_COMMIT();
    };
    // paired-lane sampling: lanes 0-15 -> pixel p, lanes 16-31 -> pixel p+1; float4/lane
    auto sampleA = [&](int tap, int buf) {
        char* Ab = abase + buf * 16384;
        int dxk = tap / 3 - 1, dyk = tap % 3 - 1;
        float rowf = (float)(i0 + dxk);
        int half = lane >> 4;      // 0/1: which pixel of the pair
        int cl = lane & 15;        // channel quad index (4 ch per lane)
#pragma unroll
        for (int it = 0; it < 4; it++) {
            int p = wid * 8 + it * 2 + half;
            float ox = OFF[tap][p];
            float oy = OFF[tap + 9][p];
            float pxf = fminf(fmaxf(rowf + ox, 0.f), 63.f);
            float pyf = fminf(fmaxf((float)(p + dyk) + oy, 0.f), 63.f);
            float fx = floorf(pxf), fy = floorf(pyf);
            int x0 = (int)fx, y0 = (int)fy;
            int x1 = min(x0 + 1, 63), y1 = min(y0 + 1, 63);
            float tfx = pxf - fx, tfy = pyf - fy;
            float w00 = (1.f - tfx) * (1.f - tfy);
            float w10 = tfx * (1.f - tfy);
            float w01 = (1.f - tfx) * tfy;
            float w11 = tfx * tfy;

            const float4* r00 = (const float4*)(gxt_b + ((x0 * WW) + y0) * CC) + cl;
            const float4* r10 = (const float4*)(gxt_b + ((x1 * WW) + y0) * CC) + cl;
            const float4* r01 = (const float4*)(gxt_b + ((x0 * WW) + y1) * CC) + cl;
            const float4* r11 = (const float4*)(gxt_b + ((x1 * WW) + y1) * CC) + cl;
            float4 a = __ldg(r00), b2 = __ldg(r10), c2 = __ldg(r01), d2 = __ldg(r11);
            float s0 = a.x * w00 + b2.x * w10 + c2.x * w01 + d2.x * w11;
            float s1 = a.y * w00 + b2.y * w10 + c2.y * w01 + d2.y * w11;
            float s2 = a.z * w00 + b2.z * w10 + c2.z * w01 + d2.z * w11;
            float s3 = a.w * w00 + b2.w * w10 + c2.w * w01 + d2.w * w11;

            __nv_bfloat162 h01 = __float22bfloat162_rn(make_float2(s0, s1));
            __nv_bfloat162 h23 = __float22bfloat162_rn(make_float2(s2, s3));
            __nv_bfloat162 l01 = __float22bfloat162_rn(
                make_float2(s0 - __bfloat162float(h01.x), s1 - __bfloat162float(h01.y)));
            __nv_bfloat162 l23 = __float22bfloat162_rn(
                make_float2(s2 - __bfloat162float(h23.x), s3 - __bfloat162float(h23.y)));

            uint32_t off = (uint32_t)p * 128 + (uint32_t)cl * 8;
            uint32_t sw = SW128(off);
            *(uint2*)(Ab + sw) = make_uint2(*(uint32_t*)&h01, *(uint32_t*)&h23);
            *(uint2*)(Ab + 8192 + sw) = make_uint2(*(uint32_t*)&l01, *(uint32_t*)&l23);
        }
    };

    __syncthreads();
    sampleA(0, 0);

    for (int n = 0; n < 9; ++n) {
        int cur = n & 1;
        __syncthreads();
        issueB(n);
        if (n + 1 < 9) sampleA(n + 1, cur ^ 1);
        CP_WAIT0();
        __syncthreads();

        uint32_t A_hi = base + cur * 16384, A_lo = A_hi + 8192;
        uint32_t B_hi = B_base, B_lo = B_base + 16384;
#pragma unroll
        for (int ks = 0; ks < 4; ks++) {
            int k0 = ks * 16;
            uint32_t ah0[4], ah1[4], al0[4], al1[4], bb[8];
            ldmA(ah0, A_hi, m0, k0, lane);
            ldmA(ah1, A_hi, m0 + 16, k0, lane);
            ldmA(al0, A_lo, m0, k0, lane);
            ldmA(al1, A_lo, m0 + 16, k0, lane);
            ldmB(bb + 0, B_hi, nbase, k0, lane);
            ldmB(bb + 4, B_hi, nbase + 16, k0, lane);
#pragma unroll
            for (int ni = 0; ni < 4; ni++) {
                const uint32_t* bf = bb + 2 * ni;
                mma16816(acc[0][ni], ah0, bf);
                mma16816(acc[1][ni], ah1, bf);
                mma16816(acc[0][ni], al0, bf);
                mma16816(acc[1][ni], al1, bf);
            }
            ldmB(bb + 0, B_lo, nbase, k0, lane);
            ldmB(bb + 4, B_lo, nbase + 16, k0, lane);
#pragma unroll
            for (int ni = 0; ni < 4; ni++) {
                const uint32_t* bf = bb + 2 * ni;
                mma16816(acc[0][ni], ah0, bf);
                mma16816(acc[1][ni], ah1, bf);
            }
        }
    }

    int gi = lane >> 2, t4 = lane & 3;
#pragma unroll
    for (int mi = 0; mi < 2; mi++) {
        int px0 = m0 + mi * 16 + gi, px1 = px0 + 8;
#pragma unroll
        for (int ni = 0; ni < 4; ni++) {
            int oc = nbase + ni * 8 + t4 * 2;
            float bv0 = __ldg(&bk[oc]), bv1 = __ldg(&bk[oc + 1]);
            float* o0 = &out[((b * OCC + oc) * HH + i0) * WW];
            float* o1 = &out[((b * OCC + oc + 1) * HH + i0) * WW];
            o0[px0] = acc[mi][ni][0] + bv0;
            o1[px0] = acc[mi][ni][1] + bv1;
            o0[px1] = acc[mi][ni][2] + bv0;
            o1[px1] = acc[mi][ni][3] + bv1;
        }
    }
}

// ---------------- launch ----------------
extern "C" void kernel_launch(void* const* d_in, const int* in_sizes, int n_in,
                              void* d_out, int out_size) {
    const float* x = (const float*)d_in[0];
    const float* Woff = (const float*)d_in[1];
    const float* boff = (const float*)d_in[2];
    const float* Wk = (const float*)d_in[3];
    const float* bk = (const float*)d_in[4];
    float* out = (float*)d_out;

    k_prep<<<1384, 256>>>(x, Wk, Woff);

    const int DSM_OFF = 6 * ATILE + 16384 + 1024;   // 68096 -> 3 CTAs/SM
    cudaFuncSetAttribute(k_off2, cudaFuncAttributeMaxDynamicSharedMemorySize, DSM_OFF);
    k_off2<<<dim3(HH, BB), 256, DSM_OFF>>>(boff);

    const int DSM = 65536 + 1024;
    cudaFuncSetAttribute(k_main, cudaFuncAttributeMaxDynamicSharedMemorySize, DSM);
    k_main<<<dim3(HH, BB), 256, DSM>>>(bk, out);
}

// round 16
// speedup vs baseline: 1.5368x; 1.5368x over previous
#include <cuda_runtime.h>
#include <cuda_bf16.h>
#include <cstdint>

// Shapes:
//  x [16,64,64,64] f32 NCHW, W_off [18,64,3,3], b_off[18], W_k [128,64,3,3], b_k[128]
//  out [16,128,64,64]

#define BB 16
#define CC 64
#define HH 64
#define WW 64
#define OCC 128
#define NOFF 18

// ---------------- scratch ----------------
__device__ float g_xt[BB * HH * WW * CC];          // NHWC x
__device__ float g_off[BB * NOFF * HH * WW];       // offsets planar
__device__ __nv_bfloat16 g_wb[9 * 2 * CC * OCC];   // k_main weights [tap][hi/lo][c][128oc] swizzled
__device__ __nv_bfloat16 g_wo2[5 * 2 * CC * 64];   // k_off weights: [pair][hi/lo][c][2taps x 32oc] swizzled

// swizzles
#define SW128(o) ((o) ^ (((o) >> 3) & 0x70))   // 128B rows
#define SWB(o)   ((o) ^ (((o) >> 4) & 0x70))   // 256B rows

__device__ __forceinline__ uint32_t smem_u32(const void* p) {
    uint32_t a;
    asm("{ .reg .u64 t; cvta.to.shared.u64 t, %1; cvt.u32.u64 %0, t; }" : "=r"(a) : "l"(p));
    return a;
}

__device__ __forceinline__ void ldmA(uint32_t* r, uint32_t base, int m0, int k0, int lane) {
    uint32_t off = (uint32_t)(m0 + (lane & 15)) * 128u + (uint32_t)(k0 + ((lane >> 4) & 1) * 8) * 2u;
    uint32_t addr = base + SW128(off);
    asm volatile("ldmatrix.sync.aligned.m8n8.x4.shared.b16 {%0,%1,%2,%3}, [%4];"
                 : "=r"(r[0]), "=r"(r[1]), "=r"(r[2]), "=r"(r[3]) : "r"(addr));
}
// B in 256B rows (k_main)
__device__ __forceinline__ void ldmB(uint32_t* r, uint32_t base, int n0, int k0, int lane) {
    uint32_t off = (uint32_t)(k0 + (lane & 15)) * 256u + (uint32_t)(n0 + ((lane >> 4) & 1) * 8) * 2u;
    uint32_t addr = base + SWB(off);
    asm volatile("ldmatrix.sync.aligned.m8n8.x4.trans.shared.b16 {%0,%1,%2,%3}, [%4];"
                 : "=r"(r[0]), "=r"(r[1]), "=r"(r[2]), "=r"(r[3]) : "r"(addr));
}
// B in 128B rows (k_off2)
__device__ __forceinline__ void ldmB2(uint32_t* r, uint32_t base, int n0, int k0, int lane) {
    uint32_t off = (uint32_t)(k0 + (lane & 15)) * 128u + (uint32_t)(n0 + ((lane >> 4) & 1) * 8) * 2u;
    uint32_t addr = base + SW128(off);
    asm volatile("ldmatrix.sync.aligned.m8n8.x4.trans.shared.b16 {%0,%1,%2,%3}, [%4];"
                 : "=r"(r[0]), "=r"(r[1]), "=r"(r[2]), "=r"(r[3]) : "r"(addr));
}
__device__ __forceinline__ void mma16816(float* c, const uint32_t* a, const uint32_t* b) {
    asm volatile("mma.sync.aligned.m16n8k16.row.col.f32.bf16.bf16.f32 "
                 "{%0,%1,%2,%3}, {%4,%5,%6,%7}, {%8,%9}, {%0,%1,%2,%3};"
                 : "+f"(c[0]), "+f"(c[1]), "+f"(c[2]), "+f"(c[3])
                 : "r"(a[0]), "r"(a[1]), "r"(a[2]), "r"(a[3]), "r"(b[0]), "r"(b[1]));
}

#define CP_ASYNC16(dst, src) \
    asm volatile("cp.async.cg.shared.global [%0], [%1], 16;" ::"r"(dst), "l"(src) : "memory")
#define CP_COMMIT() asm volatile("cp.async.commit_group;" ::: "memory")
#define CP_WAIT0()  asm volatile("cp.async.wait_group 0;" ::: "memory")

// ---------------- kernel P: fused prep (transpose + both weight repacks) ----------------
// grid: [0,1024) transpose, [1024,1312) W_k repack (288 blocks), [1312,1384) W_off repack (72)
__global__ __launch_bounds__(256) void k_prep(const float* __restrict__ x,
                                              const float* __restrict__ Wk,
                                              const float* __restrict__ Woff) {
    __shared__ float tile[64][65];
    int bx = blockIdx.x;
    int tid = threadIdx.x;

    if (bx < 1024) {
        // ---- NCHW -> NHWC transpose ----
        int b = bx >> 6, y = bx & 63;
        int lo = tid & 63, hi = tid >> 6;
#pragma unroll
        for (int rep = 0; rep < 16; rep++) {
            int c = rep * 4 + hi;
            tile[c][lo] = x[((b * CC + c) * HH + y) * WW + lo];
        }
        __syncthreads();
#pragma unroll
        for (int rep = 0; rep < 16; rep++) {
            int xcol = rep * 4 + hi;
            g_xt[((b * HH + y) * WW + xcol) * CC + lo] = tile[lo][xcol];
        }
    } else if (bx < 1312) {
        // ---- W_k -> swizzled bf16 hi/lo [tap][hi/lo][c][128oc] ----
        int idx = (bx - 1024) * 256 + tid;
        if (idx < 9 * OCC * CC) {
            int oc = idx & 127;
            int c = (idx >> 7) & 63;
            int n = idx >> 13;
            float v = Wk[(oc * CC + c) * 9 + n];
            __nv_bfloat16 hi = __float2bfloat16(v);
            __nv_bfloat16 lo = __float2bfloat16(v - __bfloat162float(hi));
            uint32_t off = (uint32_t)c * 256 + (uint32_t)oc * 2;
            uint32_t sw = SWB(off);
            g_wb[(n * 2 + 0) * (CC * OCC) + sw / 2] = hi;
            g_wb[(n * 2 + 1) * (CC * OCC) + sw / 2] = lo;
        }
    } else {
        // ---- W_off -> pair-packed swizzled bf16 hi/lo ----
        int idx = (bx - 1312) * 256 + tid;
        if (idx < 9 * CC * 32) {
            int oc = idx & 31;
            int c = (idx >> 5) & 63;
            int tap = idx >> 11;
            float v = (oc < NOFF) ? Woff[(oc * CC + c) * 9 + tap] : 0.f;
            __nv_bfloat16 hi = __float2bfloat16(v);
            __nv_bfloat16 lo = __float2bfloat16(v - __bfloat162float(hi));
            int pair = tap >> 1;
            int slot = (tap & 1) * 32 + oc;
            uint32_t sw = SW128((uint32_t)c * 128 + (uint32_t)slot * 2);
            g_wo2[(pair * 2 + 0) * (CC * 64) + sw / 2] = hi;
            g_wo2[(pair * 2 + 1) * (CC * 64) + sw / 2] = lo;
        }
    }
}

extern __shared__ char dsm_raw[];

// ---------------- kernel B: offset conv (R13 config: M=128, 2 CTAs/SM, dbuf B pairs) ----------------
// block = (b, row-pair i0b), grid 32x16. M=128 px, N=32 (18 padded), K=9x64.
// A: 4 extended row-tiles hi+lo = 67.6KB (built once).
// B: double-buffered 2x16KB per tap-PAIR via cp.async. Total ~100KB -> 2 CTAs/SM.
#define ATILE 8448   // 66 * 128 bytes
__global__ __launch_bounds__(256, 2)
void k_off2(const float* __restrict__ boff) {
    int b = blockIdx.y, i0b = blockIdx.x * 2;
    int tid = threadIdx.x, wid = tid >> 5, lane = tid & 31;
    int mw = wid >> 1, nw = wid & 1;   // m-warp 0..3 (32px), n-warp 0..1 (16oc)
    int mrow = mw >> 1;                // image row within CTA (0/1)
    int jbase = (mw & 1) * 32;         // column base of this m-warp

    uint32_t raw = smem_u32(dsm_raw);
    uint32_t base = (raw + 1023) & ~1023u;
    char* abase = dsm_raw + (base - raw);
    uint32_t A_hi = base, A_lo = base + 4 * ATILE;
    uint32_t B_base = base + 8 * ATILE;           // 67584; 2 x 16KB buffers
    const float* gxt_b = g_xt + (size_t)b * HH * WW * CC;

    // issue 16KB B pair tile (hi 8K | lo 8K) into buffer buf
    auto issueBp = [&](int pair, int buf) {
        uint32_t dst = B_base + buf * 16384 + (uint32_t)tid * 16;
        const char* src = (const char*)g_wo2 + pair * 16384 + tid * 16;
#pragma unroll
        for (int v = 0; v < 4; v++) CP_ASYNC16(dst + v * 4096, src + v * 4096);
        CP_COMMIT();
    };

    issueBp(0, 0);

    // ---- A: build 4 extended row-tiles once ----
    for (int mi = wid; mi < 4 * 66; mi += 8) {
        int tile = mi / 66, m = mi % 66;
        int row = i0b + tile - 1, col = m - 1;
        bool ok = (row >= 0) && (row < HH) && (col >= 0) && (col < WW);
        float2 v = ok ? __ldg((const float2*)(gxt_b + (row * WW + col) * CC) + lane)
                      : make_float2(0.f, 0.f);
        __nv_bfloat162 hi2 = __float22bfloat162_rn(v);
        float hxf = __bfloat162float(hi2.x), hyf = __bfloat162float(hi2.y);
        __nv_bfloat162 lo2 = __float22bfloat162_rn(make_float2(v.x - hxf, v.y - hyf));
        uint32_t sw = SW128((uint32_t)m * 128 + (uint32_t)lane * 4);
        *(__nv_bfloat162*)(abase + tile * ATILE + sw) = hi2;
        *(__nv_bfloat162*)(abase + 4 * ATILE + tile * ATILE + sw) = lo2;
    }

    float acc[2][2][4];
#pragma unroll
    for (int f = 0; f < 2; f++)
#pragma unroll
        for (int h = 0; h < 2; h++)
#pragma unroll
            for (int q = 0; q < 4; q++) acc[f][h][q] = 0.f;

#pragma unroll
    for (int pair = 0; pair < 5; pair++) {
        int cur = pair & 1;
        CP_WAIT0();          // B[pair] landed
        __syncthreads();     // publish A (first iter) + B[pair]; MMA(pair-1) done -> alt buf free
        if (pair < 4) issueBp(pair + 1, cur ^ 1);

        uint32_t Bh = B_base + cur * 16384;
        uint32_t Bl = Bh + 8192;
#pragma unroll
        for (int t2 = 0; t2 < 2; t2++) {
            int tap = pair * 2 + t2;
            if (tap >= 9) break;
            int dxk = tap / 3 - 1, dyk = tap % 3 - 1;
            int tile = mrow + dxk + 1;                  // 0..3
            uint32_t Ah = A_hi + tile * ATILE;
            uint32_t Al = A_lo + tile * ATILE;
            int n0 = t2 * 32 + nw * 16;
            int mA0 = jbase + dyk + 1;                  // frag0 m-base in tile
#pragma unroll
            for (int ks = 0; ks < 4; ks++) {
                int k0 = ks * 16;
                uint32_t ah0[4], ah1[4], al0[4], al1[4], bh[4], bl[4];
                ldmA(ah0, Ah, mA0, k0, lane);
                ldmA(ah1, Ah, mA0 + 16, k0, lane);
                ldmA(al0, Al, mA0, k0, lane);
                ldmA(al1, Al, mA0 + 16, k0, lane);
                ldmB2(bh, Bh, n0, k0, lane);
                ldmB2(bl, Bl, n0, k0, lane);
#pragma unroll
                for (int h = 0; h < 2; h++) {
                    mma16816(acc[0][h], ah0, bh + 2 * h);
                    mma16816(acc[0][h], al0, bh + 2 * h);
                    mma16816(acc[0][h], ah0, bl + 2 * h);
                    mma16816(acc[1][h], ah1, bh + 2 * h);
                    mma16816(acc[1][h], al1, bh + 2 * h);
                    mma16816(acc[1][h], ah1, bl + 2 * h);
                }
            }
        }
    }

    // ---- epilogue: oc < 18 only ----
    int gi = lane >> 2, t4 = lane & 3;
#pragma unroll
    for (int f = 0; f < 2; f++) {
        int j0 = jbase + f * 16 + gi;
        int j1 = j0 + 8;
#pragma unroll
        for (int h = 0; h < 2; h++) {
            int o = nw * 16 + h * 8 + t4 * 2;
            if (o < NOFF) {
                float bv0 = __ldg(&boff[o]);
                float* dst0 = &g_off[((b * NOFF + o) * HH + i0b + mrow) * WW];
                dst0[j0] = acc[f][h][0] + bv0;
                dst0[j1] = acc[f][h][2] + bv0;
                if (o + 1 < NOFF) {
                    float bv1 = __ldg(&boff[o + 1]);
                    float* dst1 = &g_off[((b * NOFF + o + 1) * HH + i0b + mrow) * WW];
                    dst1[j0] = acc[f][h][1] + bv1;
                    dst1[j1] = acc[f][h][3] + bv1;
                }
            }
        }
    }
}

// ---------------- kernel D: pipelined sampling (LDG.128 paired-lane) + HMMA 2m x 4n ----------------
__global__ __launch_bounds__(256, 3)
void k_main(const float* __restrict__ bk, float* __restrict__ out) {
    __shared__ float OFF[NOFF][64];

    int b = blockIdx.y, i0 = blockIdx.x;
    int tid = threadIdx.x, wid = tid >> 5, lane = tid & 31;
    int mw = wid >> 2, nw4 = wid & 3;   // 2 m-warps (32px), 4 n-warps (32oc)
    int m0 = mw * 32, nbase = nw4 * 32;

    uint32_t raw = smem_u32(dsm_raw);
    uint32_t base = (raw + 1023) & ~1023u;
    char* abase = dsm_raw + (base - raw);
    const float* gxt_b = g_xt + (size_t)b * HH * WW * CC;
    uint32_t B_base = base + 32768;

    for (int t = tid; t < NOFF * 64; t += 256) {
        int o = t >> 6, j = t & 63;
        OFF[o][j] = g_off[((b * NOFF + o) * HH + i0) * WW + j];
    }

    float acc[2][4][4];
#pragma unroll
    for (int mi = 0; mi < 2; mi++)
#pragma unroll
        for (int ni = 0; ni < 4; ni++)
#pragma unroll
            for (int q = 0; q < 4; q++) acc[mi][ni][q] = 0.f;

    auto issueB = [&](int tap) {
        uint32_t dst = B_base + (uint32_t)tid * 16;
        const char* src = (const char*)(g_wb + tap * 2 * (CC * OCC)) + tid * 16;
#pragma unroll
        for (int v = 0; v < 8; v++) CP_ASYNC16(dst + v * 4096, src + v * 4096);
        CP_COMMIT();
    };
    // paired-lane sampling: lanes 0-15 -> pixel p, lanes 16-31 -> pixel p+1; float4/lane
    auto sampleA = [&](int tap, int buf) {
        char* Ab = abase + buf * 16384;
        int dxk = tap / 3 - 1, dyk = tap % 3 - 1;
        float rowf = (float)(i0 + dxk);
        int half = lane >> 4;      // 0/1: which pixel of the pair
        int cl = lane & 15;        // channel quad index (4 ch per lane)
#pragma unroll
        for (int it = 0; it < 4; it++) {
            int p = wid * 8 + it * 2 + half;
            float ox = OFF[tap][p];
            float oy = OFF[tap + 9][p];
            float pxf = fminf(fmaxf(rowf + ox, 0.f), 63.f);
            float pyf = fminf(fmaxf((float)(p + dyk) + oy, 0.f), 63.f);
            float fx = floorf(pxf), fy = floorf(pyf);
            int x0 = (int)fx, y0 = (int)fy;
            int x1 = min(x0 + 1, 63), y1 = min(y0 + 1, 63);
            float tfx = pxf - fx, tfy = pyf - fy;
            float w00 = (1.f - tfx) * (1.f - tfy);
            float w10 = tfx * (1.f - tfy);
            float w01 = (1.f - tfx) * tfy;
            float w11 = tfx * tfy;

            const float4* r00 = (const float4*)(gxt_b + ((x0 * WW) + y0) * CC) + cl;
            const float4* r10 = (const float4*)(gxt_b + ((x1 * WW) + y0) * CC) + cl;
            const float4* r01 = (const float4*)(gxt_b + ((x0 * WW) + y1) * CC) + cl;
            const float4* r11 = (const float4*)(gxt_b + ((x1 * WW) + y1) * CC) + cl;
            float4 a = __ldg(r00), b2 = __ldg(r10), c2 = __ldg(r01), d2 = __ldg(r11);
            float s0 = a.x * w00 + b2.x * w10 + c2.x * w01 + d2.x * w11;
            float s1 = a.y * w00 + b2.y * w10 + c2.y * w01 + d2.y * w11;
            float s2 = a.z * w00 + b2.z * w10 + c2.z * w01 + d2.z * w11;
            float s3 = a.w * w00 + b2.w * w10 + c2.w * w01 + d2.w * w11;

            __nv_bfloat162 h01 = __float22bfloat162_rn(make_float2(s0, s1));
            __nv_bfloat162 h23 = __float22bfloat162_rn(make_float2(s2, s3));
            __nv_bfloat162 l01 = __float22bfloat162_rn(
                make_float2(s0 - __bfloat162float(h01.x), s1 - __bfloat162float(h01.y)));
            __nv_bfloat162 l23 = __float22bfloat162_rn(
                make_float2(s2 - __bfloat162float(h23.x), s3 - __bfloat162float(h23.y)));

            uint32_t off = (uint32_t)p * 128 + (uint32_t)cl * 8;
            uint32_t sw = SW128(off);
            *(uint2*)(Ab + sw) = make_uint2(*(uint32_t*)&h01, *(uint32_t*)&h23);
            *(uint2*)(Ab + 8192 + sw) = make_uint2(*(uint32_t*)&l01, *(uint32_t*)&l23);
        }
    };

    __syncthreads();
    sampleA(0, 0);

    for (int n = 0; n < 9; ++n) {
        int cur = n & 1;
        __syncthreads();
        issueB(n);
        if (n + 1 < 9) sampleA(n + 1, cur ^ 1);
        CP_WAIT0();
        __syncthreads();

        uint32_t A_hi = base + cur * 16384, A_lo = A_hi + 8192;
        uint32_t B_hi = B_base, B_lo = B_base + 16384;
#pragma unroll
        for (int ks = 0; ks < 4; ks++) {
            int k0 = ks * 16;
            uint32_t ah0[4], ah1[4], al0[4], al1[4], bb[8];
            ldmA(ah0, A_hi, m0, k0, lane);
            ldmA(ah1, A_hi, m0 + 16, k0, lane);
            ldmA(al0, A_lo, m0, k0, lane);
            ldmA(al1, A_lo, m0 + 16, k0, lane);
            ldmB(bb + 0, B_hi, nbase, k0, lane);
            ldmB(bb + 4, B_hi, nbase + 16, k0, lane);
#pragma unroll
            for (int ni = 0; ni < 4; ni++) {
                const uint32_t* bf = bb + 2 * ni;
                mma16816(acc[0][ni], ah0, bf);
                mma16816(acc[1][ni], ah1, bf);
                mma16816(acc[0][ni], al0, bf);
                mma16816(acc[1][ni], al1, bf);
            }
            ldmB(bb + 0, B_lo, nbase, k0, lane);
            ldmB(bb + 4, B_lo, nbase + 16, k0, lane);
#pragma unroll
            for (int ni = 0; ni < 4; ni++) {
                const uint32_t* bf = bb + 2 * ni;
                mma16816(acc[0][ni], ah0, bf);
                mma16816(acc[1][ni], ah1, bf);
            }
        }
    }

    int gi = lane >> 2, t4 = lane & 3;
#pragma unroll
    for (int mi = 0; mi < 2; mi++) {
        int px0 = m0 + mi * 16 + gi, px1 = px0 + 8;
#pragma unroll
        for (int ni = 0; ni < 4; ni++) {
            int oc = nbase + ni * 8 + t4 * 2;
            float bv0 = __ldg(&bk[oc]), bv1 = __ldg(&bk[oc + 1]);
            float* o0 = &out[((b * OCC + oc) * HH + i0) * WW];
            float* o1 = &out[((b * OCC + oc + 1) * HH + i0) * WW];
            o0[px0] = acc[mi][ni][0] + bv0;
            o1[px0] = acc[mi][ni][1] + bv1;
            o0[px1] = acc[mi][ni][2] + bv0;
            o1[px1] = acc[mi][ni][3] + bv1;
        }
    }
}

// ---------------- launch ----------------
extern "C" void kernel_launch(void* const* d_in, const int* in_sizes, int n_in,
                              void* d_out, int out_size) {
    const float* x = (const float*)d_in[0];
    const float* Woff = (const float*)d_in[1];
    const float* boff = (const float*)d_in[2];
    const float* Wk = (const float*)d_in[3];
    const float* bk = (const float*)d_in[4];
    float* out = (float*)d_out;

    k_prep<<<1384, 256>>>(x, Wk, Woff);

    const int DSM_OFF = 8 * ATILE + 32768 + 1024;   // 101376 -> 2 CTAs/SM
    cudaFuncSetAttribute(k_off2, cudaFuncAttributeMaxDynamicSharedMemorySize, DSM_OFF);
    k_off2<<<dim3(32, BB), 256, DSM_OFF>>>(boff);

    const int DSM = 65536 + 1024;
    cudaFuncSetAttribute(k_main, cudaFuncAttributeMaxDynamicSharedMemorySize, DSM);
    k_main<<<dim3(HH, BB), 256, DSM>>>(bk, out);
}

// round 17
// speedup vs baseline: 1.6283x; 1.0596x over previous
#include <cuda_runtime.h>
#include <cuda_bf16.h>
#include <cuda_fp16.h>
#include <cstdint>

// Shapes:
//  x [16,64,64,64] f32 NCHW, W_off [18,64,3,3], b_off[18], W_k [128,64,3,3], b_k[128]
//  out [16,128,64,64]

#define BB 16
#define CC 64
#define HH 64
#define WW 64
#define OCC 128
#define NOFF 18

// ---------------- scratch ----------------
__device__ float g_xt[BB * HH * WW * CC];          // NHWC x
__device__ float g_off[BB * NOFF * HH * WW];       // offsets planar
__device__ __half g_wb[9 * CC * OCC];              // k_main weights [tap][c][128oc] fp16 swizzled
__device__ __nv_bfloat16 g_wo2[5 * 2 * CC * 64];   // k_off weights: [pair][hi/lo][c][2taps x 32oc] swizzled

// swizzles
#define SW128(o) ((o) ^ (((o) >> 3) & 0x70))   // 128B rows
#define SWB(o)   ((o) ^ (((o) >> 4) & 0x70))   // 256B rows

__device__ __forceinline__ uint32_t smem_u32(const void* p) {
    uint32_t a;
    asm("{ .reg .u64 t; cvta.to.shared.u64 t, %1; cvt.u32.u64 %0, t; }" : "=r"(a) : "l"(p));
    return a;
}

__device__ __forceinline__ void ldmA(uint32_t* r, uint32_t base, int m0, int k0, int lane) {
    uint32_t off = (uint32_t)(m0 + (lane & 15)) * 128u + (uint32_t)(k0 + ((lane >> 4) & 1) * 8) * 2u;
    uint32_t addr = base + SW128(off);
    asm volatile("ldmatrix.sync.aligned.m8n8.x4.shared.b16 {%0,%1,%2,%3}, [%4];"
                 : "=r"(r[0]), "=r"(r[1]), "=r"(r[2]), "=r"(r[3]) : "r"(addr));
}
// B in 256B rows (k_main)
__device__ __forceinline__ void ldmB(uint32_t* r, uint32_t base, int n0, int k0, int lane) {
    uint32_t off = (uint32_t)(k0 + (lane & 15)) * 256u + (uint32_t)(n0 + ((lane >> 4) & 1) * 8) * 2u;
    uint32_t addr = base + SWB(off);
    asm volatile("ldmatrix.sync.aligned.m8n8.x4.trans.shared.b16 {%0,%1,%2,%3}, [%4];"
                 : "=r"(r[0]), "=r"(r[1]), "=r"(r[2]), "=r"(r[3]) : "r"(addr));
}
// B in 128B rows (k_off2)
__device__ __forceinline__ void ldmB2(uint32_t* r, uint32_t base, int n0, int k0, int lane) {
    uint32_t off = (uint32_t)(k0 + (lane & 15)) * 128u + (uint32_t)(n0 + ((lane >> 4) & 1) * 8) * 2u;
    uint32_t addr = base + SW128(off);
    asm volatile("ldmatrix.sync.aligned.m8n8.x4.trans.shared.b16 {%0,%1,%2,%3}, [%4];"
                 : "=r"(r[0]), "=r"(r[1]), "=r"(r[2]), "=r"(r[3]) : "r"(addr));
}
// bf16 mma (k_off2)
__device__ __forceinline__ void mma16816(float* c, const uint32_t* a, const uint32_t* b) {
    asm volatile("mma.sync.aligned.m16n8k16.row.col.f32.bf16.bf16.f32 "
                 "{%0,%1,%2,%3}, {%4,%5,%6,%7}, {%8,%9}, {%0,%1,%2,%3};"
                 : "+f"(c[0]), "+f"(c[1]), "+f"(c[2]), "+f"(c[3])
                 : "r"(a[0]), "r"(a[1]), "r"(a[2]), "r"(a[3]), "r"(b[0]), "r"(b[1]));
}
// fp16 mma (k_main)
__device__ __forceinline__ void mma16816h(float* c, const uint32_t* a, const uint32_t* b) {
    asm volatile("mma.sync.aligned.m16n8k16.row.col.f32.f16.f16.f32 "
                 "{%0,%1,%2,%3}, {%4,%5,%6,%7}, {%8,%9}, {%0,%1,%2,%3};"
                 : "+f"(c[0]), "+f"(c[1]), "+f"(c[2]), "+f"(c[3])
                 : "r"(a[0]), "r"(a[1]), "r"(a[2]), "r"(a[3]), "r"(b[0]), "r"(b[1]));
}

#define CP_ASYNC16(dst, src) \
    asm volatile("cp.async.cg.shared.global [%0], [%1], 16;" ::"r"(dst), "l"(src) : "memory")
#define CP_COMMIT() asm volatile("cp.async.commit_group;" ::: "memory")
#define CP_WAIT0()  asm volatile("cp.async.wait_group 0;" ::: "memory")

// ---------------- kernel P: fused prep (transpose + both weight repacks) ----------------
// grid: [0,1024) transpose, [1024,1312) W_k repack (288 blocks), [1312,1384) W_off repack (72)
__global__ __launch_bounds__(256) void k_prep(const float* __restrict__ x,
                                              const float* __restrict__ Wk,
                                              const float* __restrict__ Woff) {
    __shared__ float tile[64][65];
    int bx = blockIdx.x;
    int tid = threadIdx.x;

    if (bx < 1024) {
        // ---- NCHW -> NHWC transpose ----
        int b = bx >> 6, y = bx & 63;
        int lo = tid & 63, hi = tid >> 6;
#pragma unroll
        for (int rep = 0; rep < 16; rep++) {
            int c = rep * 4 + hi;
            tile[c][lo] = x[((b * CC + c) * HH + y) * WW + lo];
        }
        __syncthreads();
#pragma unroll
        for (int rep = 0; rep < 16; rep++) {
            int xcol = rep * 4 + hi;
            g_xt[((b * HH + y) * WW + xcol) * CC + lo] = tile[lo][xcol];
        }
    } else if (bx < 1312) {
        // ---- W_k -> swizzled fp16 [tap][c][128oc] ----
        int idx = (bx - 1024) * 256 + tid;
        if (idx < 9 * OCC * CC) {
            int oc = idx & 127;
            int c = (idx >> 7) & 63;
            int n = idx >> 13;
            float v = Wk[(oc * CC + c) * 9 + n];
            uint32_t off = (uint32_t)c * 256 + (uint32_t)oc * 2;
            uint32_t sw = SWB(off);
            g_wb[n * (CC * OCC) + sw / 2] = __float2half(v);
        }
    } else {
        // ---- W_off -> pair-packed swizzled bf16 hi/lo ----
        int idx = (bx - 1312) * 256 + tid;
        if (idx < 9 * CC * 32) {
            int oc = idx & 31;
            int c = (idx >> 5) & 63;
            int tap = idx >> 11;
            float v = (oc < NOFF) ? Woff[(oc * CC + c) * 9 + tap] : 0.f;
            __nv_bfloat16 hi = __float2bfloat16(v);
            __nv_bfloat16 lo = __float2bfloat16(v - __bfloat162float(hi));
            int pair = tap >> 1;
            int slot = (tap & 1) * 32 + oc;
            uint32_t sw = SW128((uint32_t)c * 128 + (uint32_t)slot * 2);
            g_wo2[(pair * 2 + 0) * (CC * 64) + sw / 2] = hi;
            g_wo2[(pair * 2 + 1) * (CC * 64) + sw / 2] = lo;
        }
    }
}

extern __shared__ char dsm_raw[];

// ---------------- kernel B: offset conv (R16: M=128, 2 CTAs/SM, dbuf B pairs, 3-term bf16) --------
#define ATILE 8448   // 66 * 128 bytes
__global__ __launch_bounds__(256, 2)
void k_off2(const float* __restrict__ boff) {
    int b = blockIdx.y, i0b = blockIdx.x * 2;
    int tid = threadIdx.x, wid = tid >> 5, lane = tid & 31;
    int mw = wid >> 1, nw = wid & 1;   // m-warp 0..3 (32px), n-warp 0..1 (16oc)
    int mrow = mw >> 1;                // image row within CTA (0/1)
    int jbase = (mw & 1) * 32;         // column base of this m-warp

    uint32_t raw = smem_u32(dsm_raw);
    uint32_t base = (raw + 1023) & ~1023u;
    char* abase = dsm_raw + (base - raw);
    uint32_t A_hi = base, A_lo = base + 4 * ATILE;
    uint32_t B_base = base + 8 * ATILE;           // 67584; 2 x 16KB buffers
    const float* gxt_b = g_xt + (size_t)b * HH * WW * CC;

    auto issueBp = [&](int pair, int buf) {
        uint32_t dst = B_base + buf * 16384 + (uint32_t)tid * 16;
        const char* src = (const char*)g_wo2 + pair * 16384 + tid * 16;
#pragma unroll
        for (int v = 0; v < 4; v++) CP_ASYNC16(dst + v * 4096, src + v * 4096);
        CP_COMMIT();
    };

    issueBp(0, 0);

    // ---- A: build 4 extended row-tiles once ----
    for (int mi = wid; mi < 4 * 66; mi += 8) {
        int tile = mi / 66, m = mi % 66;
        int row = i0b + tile - 1, col = m - 1;
        bool ok = (row >= 0) && (row < HH) && (col >= 0) && (col < WW);
        float2 v = ok ? __ldg((const float2*)(gxt_b + (row * WW + col) * CC) + lane)
                      : make_float2(0.f, 0.f);
        __nv_bfloat162 hi2 = __float22bfloat162_rn(v);
        float hxf = __bfloat162float(hi2.x), hyf = __bfloat162float(hi2.y);
        __nv_bfloat162 lo2 = __float22bfloat162_rn(make_float2(v.x - hxf, v.y - hyf));
        uint32_t sw = SW128((uint32_t)m * 128 + (uint32_t)lane * 4);
        *(__nv_bfloat162*)(abase + tile * ATILE + sw) = hi2;
        *(__nv_bfloat162*)(abase + 4 * ATILE + tile * ATILE + sw) = lo2;
    }

    float acc[2][2][4];
#pragma unroll
    for (int f = 0; f < 2; f++)
#pragma unroll
        for (int h = 0; h < 2; h++)
#pragma unroll
            for (int q = 0; q < 4; q++) acc[f][h][q] = 0.f;

#pragma unroll
    for (int pair = 0; pair < 5; pair++) {
        int cur = pair & 1;
        CP_WAIT0();
        __syncthreads();
        if (pair < 4) issueBp(pair + 1, cur ^ 1);

        uint32_t Bh = B_base + cur * 16384;
        uint32_t Bl = Bh + 8192;
#pragma unroll
        for (int t2 = 0; t2 < 2; t2++) {
            int tap = pair * 2 + t2;
            if (tap >= 9) break;
            int dxk = tap / 3 - 1, dyk = tap % 3 - 1;
            int tile = mrow + dxk + 1;
            uint32_t Ah = A_hi + tile * ATILE;
            uint32_t Al = A_lo + tile * ATILE;
            int n0 = t2 * 32 + nw * 16;
            int mA0 = jbase + dyk + 1;
#pragma unroll
            for (int ks = 0; ks < 4; ks++) {
                int k0 = ks * 16;
                uint32_t ah0[4], ah1[4], al0[4], al1[4], bh[4], bl[4];
                ldmA(ah0, Ah, mA0, k0, lane);
                ldmA(ah1, Ah, mA0 + 16, k0, lane);
                ldmA(al0, Al, mA0, k0, lane);
                ldmA(al1, Al, mA0 + 16, k0, lane);
                ldmB2(bh, Bh, n0, k0, lane);
                ldmB2(bl, Bl, n0, k0, lane);
#pragma unroll
                for (int h = 0; h < 2; h++) {
                    mma16816(acc[0][h], ah0, bh + 2 * h);
                    mma16816(acc[0][h], al0, bh + 2 * h);
                    mma16816(acc[0][h], ah0, bl + 2 * h);
                    mma16816(acc[1][h], ah1, bh + 2 * h);
                    mma16816(acc[1][h], al1, bh + 2 * h);
                    mma16816(acc[1][h], ah1, bl + 2 * h);
                }
            }
        }
    }

    // ---- epilogue: oc < 18 only ----
    int gi = lane >> 2, t4 = lane & 3;
#pragma unroll
    for (int f = 0; f < 2; f++) {
        int j0 = jbase + f * 16 + gi;
        int j1 = j0 + 8;
#pragma unroll
        for (int h = 0; h < 2; h++) {
            int o = nw * 16 + h * 8 + t4 * 2;
            if (o < NOFF) {
                float bv0 = __ldg(&boff[o]);
                float* dst0 = &g_off[((b * NOFF + o) * HH + i0b + mrow) * WW];
                dst0[j0] = acc[f][h][0] + bv0;
                dst0[j1] = acc[f][h][2] + bv0;
                if (o + 1 < NOFF) {
                    float bv1 = __ldg(&boff[o + 1]);
                    float* dst1 = &g_off[((b * NOFF + o + 1) * HH + i0b + mrow) * WW];
                    dst1[j0] = acc[f][h][1] + bv1;
                    dst1[j1] = acc[f][h][3] + bv1;
                }
            }
        }
    }
}

// ---------------- kernel D: fp16 single-term, A+B double-buffered, ONE sync/tap ----------------
// block = (b, row i0). M=64 px, N=128 oc, K=9x64. smem: A 2x8KB + B 2x16KB = 48KB -> 3 CTAs/SM.
__global__ __launch_bounds__(256, 3)
void k_main(const float* __restrict__ bk, float* __restrict__ out) {
    __shared__ float OFF[NOFF][64];

    int b = blockIdx.y, i0 = blockIdx.x;
    int tid = threadIdx.x, wid = tid >> 5, lane = tid & 31;
    int mw = wid >> 2, nw4 = wid & 3;   // 2 m-warps (32px), 4 n-warps (32oc)
    int m0 = mw * 32, nbase = nw4 * 32;

    uint32_t raw = smem_u32(dsm_raw);
    uint32_t base = (raw + 1023) & ~1023u;
    char* abase = dsm_raw + (base - raw);
    const float* gxt_b = g_xt + (size_t)b * HH * WW * CC;
    uint32_t Bb = base + 16384;   // B buffers at +16K (2x16KB)

    for (int t = tid; t < NOFF * 64; t += 256) {
        int o = t >> 6, j = t & 63;
        OFF[o][j] = g_off[((b * NOFF + o) * HH + i0) * WW + j];
    }

    float acc[2][4][4];
#pragma unroll
    for (int mi = 0; mi < 2; mi++)
#pragma unroll
        for (int ni = 0; ni < 4; ni++)
#pragma unroll
            for (int q = 0; q < 4; q++) acc[mi][ni][q] = 0.f;

    auto issueB = [&](int tap, int buf) {
        uint32_t dst = Bb + buf * 16384 + (uint32_t)tid * 16;
        const char* src = (const char*)(g_wb + tap * (CC * OCC)) + tid * 16;
#pragma unroll
        for (int v = 0; v < 4; v++) CP_ASYNC16(dst + v * 4096, src + v * 4096);
        CP_COMMIT();
    };
    // paired-lane sampling: lanes 0-15 -> pixel p, lanes 16-31 -> pixel p+1; float4/lane; fp16 out
    auto sampleA = [&](int tap, int buf) {
        char* Ab = abase + buf * 8192;
        int dxk = tap / 3 - 1, dyk = tap % 3 - 1;
        float rowf = (float)(i0 + dxk);
        int half = lane >> 4;
        int cl = lane & 15;
#pragma unroll
        for (int it = 0; it < 4; it++) {
            int p = wid * 8 + it * 2 + half;
            float ox = OFF[tap][p];
            float oy = OFF[tap + 9][p];
            float pxf = fminf(fmaxf(rowf + ox, 0.f), 63.f);
            float pyf = fminf(fmaxf((float)(p + dyk) + oy, 0.f), 63.f);
            float fx = floorf(pxf), fy = floorf(pyf);
            int x0 = (int)fx, y0 = (int)fy;
            int x1 = min(x0 + 1, 63), y1 = min(y0 + 1, 63);
            float tfx = pxf - fx, tfy = pyf - fy;
            float w00 = (1.f - tfx) * (1.f - tfy);
            float w10 = tfx * (1.f - tfy);
            float w01 = (1.f - tfx) * tfy;
            float w11 = tfx * tfy;

            const float4* r00 = (const float4*)(gxt_b + ((x0 * WW) + y0) * CC) + cl;
            const float4* r10 = (const float4*)(gxt_b + ((x1 * WW) + y0) * CC) + cl;
            const float4* r01 = (const float4*)(gxt_b + ((x0 * WW) + y1) * CC) + cl;
            const float4* r11 = (const float4*)(gxt_b + ((x1 * WW) + y1) * CC) + cl;
            float4 a = __ldg(r00), b2 = __ldg(r10), c2 = __ldg(r01), d2 = __ldg(r11);
            float s0 = a.x * w00 + b2.x * w10 + c2.x * w01 + d2.x * w11;
            float s1 = a.y * w00 + b2.y * w10 + c2.y * w01 + d2.y * w11;
            float s2 = a.z * w00 + b2.z * w10 + c2.z * w01 + d2.z * w11;
            float s3 = a.w * w00 + b2.w * w10 + c2.w * w01 + d2.w * w11;

            __half2 h01 = __floats2half2_rn(s0, s1);
            __half2 h23 = __floats2half2_rn(s2, s3);

            uint32_t off = (uint32_t)p * 128 + (uint32_t)cl * 8;
            uint32_t sw = SW128(off);
            *(uint2*)(Ab + sw) = make_uint2(*(uint32_t*)&h01, *(uint32_t*)&h23);
        }
    };

    __syncthreads();   // OFF published
    issueB(0, 0);
    sampleA(0, 0);

    for (int n = 0; n < 9; ++n) {
        int cur = n & 1;
        CP_WAIT0();          // B[n] landed
        __syncthreads();     // publish A[n] + B[n]; MMA(n-1) done -> alt buffers free
        if (n + 1 < 9) {
            issueB(n + 1, cur ^ 1);
            sampleA(n + 1, cur ^ 1);
        }

        uint32_t A_cur = base + cur * 8192;
        uint32_t B_cur = Bb + cur * 16384;
#pragma unroll
        for (int ks = 0; ks < 4; ks++) {
            int k0 = ks * 16;
            uint32_t ah0[4], ah1[4], bb2[8];
            ldmA(ah0, A_cur, m0, k0, lane);
            ldmA(ah1, A_cur, m0 + 16, k0, lane);
            ldmB(bb2 + 0, B_cur, nbase, k0, lane);
            ldmB(bb2 + 4, B_cur, nbase + 16, k0, lane);
#pragma unroll
            for (int ni = 0; ni < 4; ni++) {
                const uint32_t* bf = bb2 + 2 * ni;
                mma16816h(acc[0][ni], ah0, bf);
                mma16816h(acc[1][ni], ah1, bf);
            }
        }
    }

    int gi = lane >> 2, t4 = lane & 3;
#pragma unroll
    for (int mi = 0; mi < 2; mi++) {
        int px0 = m0 + mi * 16 + gi, px1 = px0 + 8;
#pragma unroll
        for (int ni = 0; ni < 4; ni++) {
            int oc = nbase + ni * 8 + t4 * 2;
            float bv0 = __ldg(&bk[oc]), bv1 = __ldg(&bk[oc + 1]);
            float* o0 = &out[((b * OCC + oc) * HH + i0) * WW];
            float* o1 = &out[((b * OCC + oc + 1) * HH + i0) * WW];
            o0[px0] = acc[mi][ni][0] + bv0;
            o1[px0] = acc[mi][ni][1] + bv1;
            o0[px1] = acc[mi][ni][2] + bv0;
            o1[px1] = acc[mi][ni][3] + bv1;
        }
    }
}

// ---------------- launch ----------------
extern "C" void kernel_launch(void* const* d_in, const int* in_sizes, int n_in,
                              void* d_out, int out_size) {
    const float* x = (const float*)d_in[0];
    const float* Woff = (const float*)d_in[1];
    const float* boff = (const float*)d_in[2];
    const float* Wk = (const float*)d_in[3];
    const float* bk = (const float*)d_in[4];
    float* out = (float*)d_out;

    k_prep<<<1384, 256>>>(x, Wk, Woff);

    const int DSM_OFF = 8 * ATILE + 32768 + 1024;   // 101376 -> 2 CTAs/SM
    cudaFuncSetAttribute(k_off2, cudaFuncAttributeMaxDynamicSharedMemorySize, DSM_OFF);
    k_off2<<<dim3(32, BB), 256, DSM_OFF>>>(boff);

    const int DSM = 49152 + 1024;                   // A 16K + B 32K -> 3 CTAs/SM
    cudaFuncSetAttribute(k_main, cudaFuncAttributeMaxDynamicSharedMemorySize, DSM);
    k_main<<<dim3(HH, BB), 256, DSM>>>(bk, out);
}